// round 1
// baseline (speedup 1.0000x reference)
#include <cuda_runtime.h>
#include <math.h>

typedef unsigned long long ull;

#define NTOK 4096      // B*L
#define NOUT 128       // 2*D
#define XSTRIDE 260    // padded smem row stride (floats), 16B-aligned, bank-spread

// scratch (static __device__ arrays: allocation-free)
__device__ float g_hidc[NTOK * NOUT];    // per-token hidden contribution (+b1)
__device__ float g_statw[12 * NOUT];     // column sums of the 12 stat blocks of W1

// ---- packed fp32x2 helpers (Blackwell FFMA2 path, PTX-only) ----
__device__ __forceinline__ void fma2(ull& d, ull a, ull b) {
    asm("fma.rn.f32x2 %0, %1, %2, %0;" : "+l"(d) : "l"(a), "l"(b));
}
__device__ __forceinline__ ull pack2(float lo, float hi) {
    ull r;
    asm("mov.b64 %0, {%1, %2};" : "=l"(r) : "r"(__float_as_uint(lo)), "r"(__float_as_uint(hi)));
    return r;
}
__device__ __forceinline__ float2 unpack2(ull v) {
    unsigned int a, b;
    asm("mov.b64 {%0, %1}, %2;" : "=r"(a), "=r"(b) : "l"(v));
    return make_float2(__uint_as_float(a), __uint_as_float(b));
}

// ============================================================================
// K0: column sums of the 12 stat blocks of W1 (rows 1024 + p*192 + s*64, 64 rows each)
// ============================================================================
__global__ void k_statw(const float* __restrict__ W1) {
    int blk = blockIdx.x;            // 0..11 = p*3+s
    int o = threadIdx.x;             // 0..127
    int row0 = 1024 + (blk / 3) * 192 + (blk % 3) * 64;
    float s = 0.f;
#pragma unroll 8
    for (int d = 0; d < 64; ++d) s += W1[(size_t)(row0 + d) * NOUT + o];
    g_statw[blk * NOUT + o] = s;
}

// ============================================================================
// K1: hidden GEMM  hidc[token][o] = sum_i hidden[token][i] * W1[i][o] + b1[o]
//   M=4096, K=1024, N=128. CTA: 128 thr = 4 warps. warp = (token-group, o-half).
//   warp covers 64 outputs (float2/lane), 8 tokens; K packed in f32x2 pairs.
// ============================================================================
__global__ void __launch_bounds__(128) k_hid(const float* __restrict__ hidden,
                                             const float* __restrict__ W1,
                                             const float* __restrict__ b1) {
    __shared__ float sh[16 * 128];   // 16 tokens x 128-wide K chunk
    int tid = threadIdx.x;
    int lane = tid & 31, w = tid >> 5;
    int tg = w >> 1, half = w & 1;
    int tok0 = blockIdx.x * 16;

    ull acc[8][2];
#pragma unroll
    for (int t = 0; t < 8; ++t) { acc[t][0] = 0ull; acc[t][1] = 0ull; }

    const float2* W1f2 = (const float2*)W1;
    int wcol = half * 32 + lane;     // float2 column index (0..63)

    for (int kc = 0; kc < 8; ++kc) {
        // stage 16x128 hidden chunk (keeps warps lockstep -> W1 L1 sharing)
#pragma unroll
        for (int r = 0; r < 4; ++r) {
            int q = tid + 128 * r;           // 0..511 float4s
            int tl = q >> 5, j4 = q & 31;
            ((float4*)sh)[tl * 32 + j4] =
                ((const float4*)hidden)[(size_t)(tok0 + tl) * 256 + kc * 32 + j4];
        }
        __syncthreads();
#pragma unroll 2
        for (int ip = 0; ip < 64; ++ip) {
            int r0 = kc * 128 + 2 * ip;
            float2 wa = W1f2[(size_t)r0 * 64 + wcol];
            float2 wb = W1f2[(size_t)r0 * 64 + 64 + wcol];
            ull wp0 = pack2(wa.x, wb.x);     // pair over K: (row i, row i+1)
            ull wp1 = pack2(wa.y, wb.y);
#pragma unroll
            for (int t = 0; t < 8; ++t) {
                int tl = tg * 8 + t;
                ull x2 = *(const ull*)&sh[tl * 128 + 2 * ip];   // LDS.64 broadcast
                fma2(acc[t][0], wp0, x2);
                fma2(acc[t][1], wp1, x2);
            }
        }
        __syncthreads();
    }
    float2 bb = ((const float2*)b1)[wcol];
#pragma unroll
    for (int t = 0; t < 8; ++t) {
        float2 a0 = unpack2(acc[t][0]);
        float2 a1 = unpack2(acc[t][1]);
        float2 o;
        o.x = a0.x + a0.y + bb.x;
        o.y = a1.x + a1.y + bb.y;
        int token = tok0 + tg * 8 + t;
        *(float2*)&g_hidc[(size_t)token * 128 + 2 * wcol] = o;
    }
}

// ============================================================================
// K2: per-head tail GEMM + stats + gelu + W2 + softmax/floor epilogue
//   CTA: 256 thr = 8 warps, 4 tokens. warp = (token, o-half), 16 heads.
// ============================================================================
__global__ void __launch_bounds__(256) k_tail(
    const float* __restrict__ br0, const float* __restrict__ br1,
    const float* __restrict__ br2, const float* __restrict__ br3,
    const float* __restrict__ W1, const float* __restrict__ W2,
    const float* __restrict__ b2, const float* __restrict__ epsf,
    const float* __restrict__ temp, float* __restrict__ out)
{
    extern __shared__ float sh[];
    float* shx = sh;                       // 64 rows (token-head) x XSTRIDE; row = concat(x0,x1,x2,x3)
    float* shstat = sh + 64 * XSTRIDE;     // 64 x 12 stats
    float* shpart = shstat + 64 * 12;      // 8 warps x 16 heads x 4 partial logits

    int tid = threadIdx.x, lane = tid & 31, w = tid >> 5;
    int tok0 = blockIdx.x * 4;

    // cooperative load of branch data: 4 tokens x 16 heads x 4 branches x 64
    const float* brs[4] = {br0, br1, br2, br3};
#pragma unroll
    for (int p = 0; p < 4; ++p) {
        const float4* src = (const float4*)(brs[p]) + (size_t)tok0 * 256;  // 1024 f4
#pragma unroll
        for (int r = 0; r < 4; ++r) {
            int q = tid + 256 * r;          // 0..1023
            int tl = q >> 4, d4 = q & 15;   // head-row, float4 within 64-block
            *(float4*)&shx[tl * XSTRIDE + p * 64 + d4 * 4] = src[q];
        }
    }
    __syncthreads();

    // stats: one thread per (branch, head-row)
    {
        int p = tid >> 6, hl = tid & 63;
        const float* xr = &shx[hl * XSTRIDE + p * 64];
        float s = 0.f, s2 = 0.f, mx = -INFINITY;
#pragma unroll 8
        for (int j = 0; j < 64; ++j) {
            float v = xr[j];
            s += v; s2 = fmaf(v, v, s2); mx = fmaxf(mx, v);
        }
        shstat[hl * 12 + p * 3 + 0] = s * 0.015625f;
        shstat[hl * 12 + p * 3 + 1] = sqrtf(fmaxf(s2 * 0.015625f, 1e-8f));
        shstat[hl * 12 + p * 3 + 2] = mx;
    }
    __syncthreads();

    int tl = w >> 1, half = w & 1;
    int token = tok0 + tl;
    int wcol = half * 32 + lane;            // float2 output column (0..63)

    ull acc[16][2];
#pragma unroll
    for (int h = 0; h < 16; ++h) { acc[h][0] = 0ull; acc[h][1] = 0ull; }

    const float2* W1f2 = (const float2*)W1;
    const float* xbase = &shx[tl * 16 * XSTRIDE];
#pragma unroll 2
    for (int ip = 0; ip < 128; ++ip) {
        int r0 = 1792 + 2 * ip;
        float2 wa = W1f2[(size_t)r0 * 64 + wcol];
        float2 wb = W1f2[(size_t)r0 * 64 + 64 + wcol];
        ull wp0 = pack2(wa.x, wb.x);
        ull wp1 = pack2(wa.y, wb.y);
#pragma unroll
        for (int h = 0; h < 16; ++h) {
            ull x2 = *(const ull*)&xbase[h * XSTRIDE + 2 * ip];  // LDS.64 broadcast
            fma2(acc[h][0], wp0, x2);
            fma2(acc[h][1], wp1, x2);
        }
    }

    // epilogue phase 1: h1 = tail + hidc(+b1) + stats·statw ; gelu ; partial W2 logits
    float2 hc = *(const float2*)&g_hidc[(size_t)token * 128 + 2 * wcol];
    const float4* W2f4 = (const float4*)W2;
#pragma unroll
    for (int h = 0; h < 16; ++h) {
        int hl = tl * 16 + h;
        float2 a0 = unpack2(acc[h][0]);
        float2 a1 = unpack2(acc[h][1]);
        float v0 = a0.x + a0.y + hc.x;
        float v1 = a1.x + a1.y + hc.y;
#pragma unroll
        for (int k = 0; k < 12; ++k) {
            float sv = shstat[hl * 12 + k];
            float2 wv = *(const float2*)&g_statw[k * 128 + 2 * wcol];
            v0 = fmaf(sv, wv.x, v0);
            v1 = fmaf(sv, wv.y, v1);
        }
        // exact gelu: x * Phi(x)
        v0 = v0 * normcdff(v0);
        v1 = v1 * normcdff(v1);
        float4 w2a = W2f4[2 * wcol];
        float4 w2b = W2f4[2 * wcol + 1];
        float p0 = v0 * w2a.x + v1 * w2b.x;
        float p1 = v0 * w2a.y + v1 * w2b.y;
        float p2 = v0 * w2a.z + v1 * w2b.z;
        float p3 = v0 * w2a.w + v1 * w2b.w;
#pragma unroll
        for (int d = 16; d > 0; d >>= 1) {
            p0 += __shfl_xor_sync(0xffffffffu, p0, d);
            p1 += __shfl_xor_sync(0xffffffffu, p1, d);
            p2 += __shfl_xor_sync(0xffffffffu, p2, d);
            p3 += __shfl_xor_sync(0xffffffffu, p3, d);
        }
        if (lane == 0) {
            float* dst = &shpart[(w * 16 + h) * 4];
            dst[0] = p0; dst[1] = p1; dst[2] = p2; dst[3] = p3;
        }
    }
    __syncthreads();

    // phase 2: combine the two o-halves, softmax/temp/floor/renorm, write
    if (tid < 64) {
        int tl2 = tid >> 4, hidx = tid & 15;
        int wa = tl2 * 2, wb = tl2 * 2 + 1;
        float l0 = shpart[(wa * 16 + hidx) * 4 + 0] + shpart[(wb * 16 + hidx) * 4 + 0] + b2[0];
        float l1 = shpart[(wa * 16 + hidx) * 4 + 1] + shpart[(wb * 16 + hidx) * 4 + 1] + b2[1];
        float l2 = shpart[(wa * 16 + hidx) * 4 + 2] + shpart[(wb * 16 + hidx) * 4 + 2] + b2[2];
        float l3 = shpart[(wa * 16 + hidx) * 4 + 3] + shpart[(wb * 16 + hidx) * 4 + 3] + b2[3];
        float tt = fminf(fmaxf(temp[hidx], 0.2f), 10.f);
        float it = 1.f / tt;
        float m = fmaxf(fmaxf(l0, l1), fmaxf(l2, l3));
        float e0 = expf((l0 - m) * it);
        float e1 = expf((l1 - m) * it);
        float e2 = expf((l2 - m) * it);
        float e3 = expf((l3 - m) * it);
        float inv = 1.f / (e0 + e1 + e2 + e3);
        float q0 = e0 * inv, q1 = e1 * inv, q2 = e2 * inv, q3 = e3 * inv;
        q0 = fmaxf(q0, fminf(fmaxf(epsf[hidx * 4 + 0], 1e-7f), 0.1f));
        q1 = fmaxf(q1, fminf(fmaxf(epsf[hidx * 4 + 1], 1e-7f), 0.1f));
        q2 = fmaxf(q2, fminf(fmaxf(epsf[hidx * 4 + 2], 1e-7f), 0.1f));
        q3 = fmaxf(q3, fminf(fmaxf(epsf[hidx * 4 + 3], 1e-7f), 0.1f));
        inv = 1.f / (q0 + q1 + q2 + q3);
        float4 res = make_float4(q0 * inv, q1 * inv, q2 * inv, q3 * inv);
        int token2 = tok0 + tl2;
        *(float4*)&out[((size_t)token2 * 16 + hidx) * 4] = res;
    }
}

extern "C" void kernel_launch(void* const* d_in, const int* in_sizes, int n_in,
                              void* d_out, int out_size) {
    const float* hidden = (const float*)d_in[0];
    const float* br0    = (const float*)d_in[1];
    const float* br1    = (const float*)d_in[2];
    const float* br2    = (const float*)d_in[3];
    const float* br3    = (const float*)d_in[4];
    const float* W1     = (const float*)d_in[5];
    const float* b1     = (const float*)d_in[6];
    const float* W2     = (const float*)d_in[7];
    const float* b2     = (const float*)d_in[8];
    const float* epsf   = (const float*)d_in[9];
    const float* temp   = (const float*)d_in[10];
    float* out = (float*)d_out;

    const int smem_tail = (64 * XSTRIDE + 64 * 12 + 8 * 16 * 4) * (int)sizeof(float); // 71680 B
    cudaFuncSetAttribute(k_tail, cudaFuncAttributeMaxDynamicSharedMemorySize, smem_tail);

    k_statw<<<12, 128>>>(W1);
    k_hid<<<256, 128>>>(hidden, W1, b1);
    k_tail<<<1024, 256, smem_tail>>>(br0, br1, br2, br3, W1, W2, b2, epsf, temp, out);
}

// round 2
// speedup vs baseline: 1.2136x; 1.2136x over previous
#include <cuda_runtime.h>
#include <math.h>

typedef unsigned long long ull;

#define NTOK 4096      // B*L
#define NOUT 128       // 2*D
#define XSTRIDE 260    // padded smem row stride (floats), 16B-aligned

// scratch (static __device__ arrays: allocation-free)
__device__ float g_hidc[NTOK * NOUT];    // per-token hidden contribution (+b1)
__device__ float g_statw[12 * NOUT];     // column sums of the 12 stat blocks of W1

// ---- packed fp32x2 helpers (Blackwell FFMA2 path, PTX-only) ----
__device__ __forceinline__ void fma2(ull& d, ull a, ull b) {
    asm("fma.rn.f32x2 %0, %1, %2, %0;" : "+l"(d) : "l"(a), "l"(b));
}
__device__ __forceinline__ ull pack2(float lo, float hi) {
    ull r;
    asm("mov.b64 %0, {%1, %2};" : "=l"(r) : "r"(__float_as_uint(lo)), "r"(__float_as_uint(hi)));
    return r;
}
__device__ __forceinline__ float2 unpack2(ull v) {
    unsigned int a, b;
    asm("mov.b64 {%0, %1}, %2;" : "=r"(a), "=r"(b) : "l"(v));
    return make_float2(__uint_as_float(a), __uint_as_float(b));
}

// ---- cp.async helpers ----
__device__ __forceinline__ void cpa16(unsigned s, const void* g) {
    asm volatile("cp.async.cg.shared.global [%0], [%1], 16;" :: "r"(s), "l"(g));
}
__device__ __forceinline__ void cpa_commit() { asm volatile("cp.async.commit_group;"); }
__device__ __forceinline__ void cpa_wait_all() { asm volatile("cp.async.wait_group 0;"); }

// ============================================================================
// K1: hidden GEMM (+ merged statw blocks)
//   main blocks (0..127): 32 tokens/CTA, 128 thr = 4 warps.
//   warp = (token-group of 16, output-half of 64). K staged in 64-row chunks.
//   statw blocks (128..139): column sums of the 12 stat blocks of W1.
// ============================================================================
__global__ void __launch_bounds__(128, 2) k_hid(const float* __restrict__ hidden,
                                                const float* __restrict__ W1,
                                                const float* __restrict__ b1) {
    if (blockIdx.x >= 128) {                 // ---- statw path ----
        int blk = blockIdx.x - 128;          // 0..11 = p*3+s
        int o = threadIdx.x;                 // 0..127
        int row0 = 1024 + (blk / 3) * 192 + (blk % 3) * 64;
        float s = 0.f;
#pragma unroll 8
        for (int d = 0; d < 64; ++d) s += W1[(size_t)(row0 + d) * NOUT + o];
        g_statw[blk * NOUT + o] = s;
        return;
    }

    extern __shared__ float sh[];
    float* xb = sh;                          // 2 buffers x 32 tokens x 64 K
    float* Wb = sh + 2 * 32 * 64;            // 2 buffers x 64 rows x 128 cols

    int tid = threadIdx.x;
    int lane = tid & 31, w = tid >> 5;
    int tg = w >> 1, half = w & 1;
    int wcol = half * 32 + lane;             // float2 output column (0..63)
    int tok0 = blockIdx.x * 32;

    unsigned xb_s = (unsigned)__cvta_generic_to_shared(xb);
    unsigned Wb_s = (unsigned)__cvta_generic_to_shared(Wb);

    // stage chunk 0 (x + W)
    {
        const float4* xs = (const float4*)(hidden) + (size_t)tok0 * 256;  // per token 256 f4, chunk = 16 f4
#pragma unroll
        for (int r = 0; r < 4; ++r) {
            int q = tid + 128 * r;           // 0..511
            int t = q >> 4, f = q & 15;
            cpa16(xb_s + (t * 64 + f * 4) * 4, xs + (size_t)t * 256 + f);
        }
        const float4* ws = (const float4*)(W1);   // rows 0..63
#pragma unroll
        for (int r = 0; r < 16; ++r) {
            int q = tid + 128 * r;           // 0..2047
            cpa16(Wb_s + q * 16, ws + q);
        }
        cpa_commit();
    }

    ull acc[16][2];
#pragma unroll
    for (int t = 0; t < 16; ++t) { acc[t][0] = 0ull; acc[t][1] = 0ull; }

    cpa_wait_all();
    __syncthreads();

    for (int kc = 0; kc < 16; ++kc) {
        int cur = kc & 1, nxt = cur ^ 1;
        if (kc < 15) {                       // prefetch next chunk
            const float4* xs = (const float4*)(hidden) + (size_t)tok0 * 256 + (kc + 1) * 16;
#pragma unroll
            for (int r = 0; r < 4; ++r) {
                int q = tid + 128 * r;
                int t = q >> 4, f = q & 15;
                cpa16(xb_s + (nxt * 2048 + t * 64 + f * 4) * 4, xs + (size_t)t * 256 + f);
            }
            const float4* ws = (const float4*)(W1) + (size_t)(kc + 1) * 2048;
#pragma unroll
            for (int r = 0; r < 16; ++r) {
                int q = tid + 128 * r;
                cpa16(Wb_s + (nxt * 8192 + q * 4) * 4, ws + q);
            }
            cpa_commit();
        }
        // compute chunk kc: 16 j-groups of 4 K-rows
        const float2* Wc = (const float2*)(Wb + cur * 8192);
        const float* xc = xb + cur * 2048 + tg * 16 * 64;
#pragma unroll 4
        for (int j = 0; j < 16; ++j) {
            float2 wa0 = Wc[(4 * j + 0) * 64 + wcol];
            float2 wb0 = Wc[(4 * j + 1) * 64 + wcol];
            float2 wa1 = Wc[(4 * j + 2) * 64 + wcol];
            float2 wb1 = Wc[(4 * j + 3) * 64 + wcol];
            ull wp00 = pack2(wa0.x, wb0.x), wp01 = pack2(wa0.y, wb0.y);
            ull wp10 = pack2(wa1.x, wb1.x), wp11 = pack2(wa1.y, wb1.y);
#pragma unroll
            for (int t = 0; t < 16; ++t) {
                ulonglong2 x = *(const ulonglong2*)&xc[t * 64 + 4 * j];
                fma2(acc[t][0], wp00, x.x);
                fma2(acc[t][1], wp01, x.x);
                fma2(acc[t][0], wp10, x.y);
                fma2(acc[t][1], wp11, x.y);
            }
        }
        if (kc < 15) cpa_wait_all();
        __syncthreads();
    }

    float2 bb = ((const float2*)b1)[wcol];
#pragma unroll
    for (int t = 0; t < 16; ++t) {
        float2 a0 = unpack2(acc[t][0]);
        float2 a1 = unpack2(acc[t][1]);
        float2 o;
        o.x = a0.x + a0.y + bb.x;
        o.y = a1.x + a1.y + bb.y;
        int token = tok0 + tg * 16 + t;
        *(float2*)&g_hidc[(size_t)token * 128 + 2 * wcol] = o;
    }
}

// ============================================================================
// K2: per-head tail GEMM + stats + gelu + W2 + softmax/floor epilogue
//   CTA: 256 thr = 8 warps, 4 tokens. warp = (token, o-half), 16 heads.
//   W1 tail staged in smem via cp.async double buffer (4 chunks of 64 rows).
// ============================================================================
__global__ void __launch_bounds__(256, 1) k_tail(
    const float* __restrict__ br0, const float* __restrict__ br1,
    const float* __restrict__ br2, const float* __restrict__ br3,
    const float* __restrict__ W1, const float* __restrict__ W2,
    const float* __restrict__ b2, const float* __restrict__ epsf,
    const float* __restrict__ temp, float* __restrict__ out)
{
    extern __shared__ float sh[];
    float* shx = sh;                       // 64 rows (token-head) x XSTRIDE
    float* shstat = shx + 64 * XSTRIDE;    // 64 x 12
    float* shpart = shstat + 64 * 12;      // 8 warps x 16 heads x 4
    float* shW = shpart + 8 * 16 * 4;      // 2 buffers x 64 rows x 128 cols

    int tid = threadIdx.x, lane = tid & 31, w = tid >> 5;
    int tok0 = blockIdx.x * 4;
    unsigned shW_s = (unsigned)__cvta_generic_to_shared(shW);

    // stage W chunk 0 (rows 1792..1855)
    {
        const float4* ws = (const float4*)(W1) + (size_t)1792 * 32;
#pragma unroll
        for (int r = 0; r < 8; ++r) {
            int q = tid + 256 * r;           // 0..2047
            cpa16(shW_s + q * 16, ws + q);
        }
        cpa_commit();
    }

    // cooperative load of branch data: 4 tokens x 16 heads x 4 branches x 64
    const float* brs[4] = {br0, br1, br2, br3};
#pragma unroll
    for (int p = 0; p < 4; ++p) {
        const float4* src = (const float4*)(brs[p]) + (size_t)tok0 * 256;  // 1024 f4
#pragma unroll
        for (int r = 0; r < 4; ++r) {
            int q = tid + 256 * r;          // 0..1023
            int tl = q >> 4, d4 = q & 15;   // head-row, float4 within 64-block
            *(float4*)&shx[tl * XSTRIDE + p * 64 + d4 * 4] = src[q];
        }
    }
    __syncthreads();

    // stats: one thread per (branch, head-row)
    {
        int p = tid >> 6, hl = tid & 63;
        const float* xr = &shx[hl * XSTRIDE + p * 64];
        float s = 0.f, s2 = 0.f, mx = -INFINITY;
#pragma unroll 8
        for (int j = 0; j < 64; ++j) {
            float v = xr[j];
            s += v; s2 = fmaf(v, v, s2); mx = fmaxf(mx, v);
        }
        shstat[hl * 12 + p * 3 + 0] = s * 0.015625f;
        shstat[hl * 12 + p * 3 + 1] = sqrtf(fmaxf(s2 * 0.015625f, 1e-8f));
        shstat[hl * 12 + p * 3 + 2] = mx;
    }
    cpa_wait_all();
    __syncthreads();

    int tl = w >> 1, half = w & 1;
    int token = tok0 + tl;
    int wcol = half * 32 + lane;            // float2 output column (0..63)

    ull acc[16][2];
#pragma unroll
    for (int h = 0; h < 16; ++h) { acc[h][0] = 0ull; acc[h][1] = 0ull; }

    const float* xbase = &shx[tl * 16 * XSTRIDE];

    for (int kc = 0; kc < 4; ++kc) {
        int cur = kc & 1, nxt = cur ^ 1;
        if (kc < 3) {                        // prefetch next W chunk
            const float4* ws = (const float4*)(W1) + (size_t)(1792 + (kc + 1) * 64) * 32;
#pragma unroll
            for (int r = 0; r < 8; ++r) {
                int q = tid + 256 * r;
                cpa16(shW_s + (nxt * 8192 + q * 4) * 4, ws + q);
            }
            cpa_commit();
        }
        const float2* Wc = (const float2*)(shW + cur * 8192);
        const float* xc = xbase + kc * 64;
#pragma unroll 4
        for (int j = 0; j < 16; ++j) {
            float2 wa0 = Wc[(4 * j + 0) * 64 + wcol];
            float2 wb0 = Wc[(4 * j + 1) * 64 + wcol];
            float2 wa1 = Wc[(4 * j + 2) * 64 + wcol];
            float2 wb1 = Wc[(4 * j + 3) * 64 + wcol];
            ull wp00 = pack2(wa0.x, wb0.x), wp01 = pack2(wa0.y, wb0.y);
            ull wp10 = pack2(wa1.x, wb1.x), wp11 = pack2(wa1.y, wb1.y);
#pragma unroll
            for (int h = 0; h < 16; ++h) {
                ulonglong2 x = *(const ulonglong2*)&xc[h * XSTRIDE + 4 * j];
                fma2(acc[h][0], wp00, x.x);
                fma2(acc[h][1], wp01, x.x);
                fma2(acc[h][0], wp10, x.y);
                fma2(acc[h][1], wp11, x.y);
            }
        }
        if (kc < 3) cpa_wait_all();
        __syncthreads();
    }

    // epilogue phase 1: h1 = tail + hidc(+b1) + stats·statw ; gelu ; partial W2 logits
    float2 hc = *(const float2*)&g_hidc[(size_t)token * 128 + 2 * wcol];
    const float4* W2f4 = (const float4*)W2;
#pragma unroll
    for (int h = 0; h < 16; ++h) {
        int hl = tl * 16 + h;
        float2 a0 = unpack2(acc[h][0]);
        float2 a1 = unpack2(acc[h][1]);
        float v0 = a0.x + a0.y + hc.x;
        float v1 = a1.x + a1.y + hc.y;
#pragma unroll
        for (int k = 0; k < 12; ++k) {
            float sv = shstat[hl * 12 + k];
            float2 wv = *(const float2*)&g_statw[k * 128 + 2 * wcol];
            v0 = fmaf(sv, wv.x, v0);
            v1 = fmaf(sv, wv.y, v1);
        }
        // exact gelu: x * Phi(x)
        v0 = v0 * normcdff(v0);
        v1 = v1 * normcdff(v1);
        float4 w2a = W2f4[2 * wcol];
        float4 w2b = W2f4[2 * wcol + 1];
        float p0 = v0 * w2a.x + v1 * w2b.x;
        float p1 = v0 * w2a.y + v1 * w2b.y;
        float p2 = v0 * w2a.z + v1 * w2b.z;
        float p3 = v0 * w2a.w + v1 * w2b.w;
#pragma unroll
        for (int d = 16; d > 0; d >>= 1) {
            p0 += __shfl_xor_sync(0xffffffffu, p0, d);
            p1 += __shfl_xor_sync(0xffffffffu, p1, d);
            p2 += __shfl_xor_sync(0xffffffffu, p2, d);
            p3 += __shfl_xor_sync(0xffffffffu, p3, d);
        }
        if (lane == 0) {
            float* dst = &shpart[(w * 16 + h) * 4];
            dst[0] = p0; dst[1] = p1; dst[2] = p2; dst[3] = p3;
        }
    }
    __syncthreads();

    // phase 2: combine the two o-halves, softmax/temp/floor/renorm, write
    if (tid < 64) {
        int tl2 = tid >> 4, hidx = tid & 15;
        int wa = tl2 * 2, wb = tl2 * 2 + 1;
        float l0 = shpart[(wa * 16 + hidx) * 4 + 0] + shpart[(wb * 16 + hidx) * 4 + 0] + b2[0];
        float l1 = shpart[(wa * 16 + hidx) * 4 + 1] + shpart[(wb * 16 + hidx) * 4 + 1] + b2[1];
        float l2 = shpart[(wa * 16 + hidx) * 4 + 2] + shpart[(wb * 16 + hidx) * 4 + 2] + b2[2];
        float l3 = shpart[(wa * 16 + hidx) * 4 + 3] + shpart[(wb * 16 + hidx) * 4 + 3] + b2[3];
        float tt = fminf(fmaxf(temp[hidx], 0.2f), 10.f);
        float it = 1.f / tt;
        float m = fmaxf(fmaxf(l0, l1), fmaxf(l2, l3));
        float e0 = expf((l0 - m) * it);
        float e1 = expf((l1 - m) * it);
        float e2 = expf((l2 - m) * it);
        float e3 = expf((l3 - m) * it);
        float inv = 1.f / (e0 + e1 + e2 + e3);
        float q0 = e0 * inv, q1 = e1 * inv, q2 = e2 * inv, q3 = e3 * inv;
        q0 = fmaxf(q0, fminf(fmaxf(epsf[hidx * 4 + 0], 1e-7f), 0.1f));
        q1 = fmaxf(q1, fminf(fmaxf(epsf[hidx * 4 + 1], 1e-7f), 0.1f));
        q2 = fmaxf(q2, fminf(fmaxf(epsf[hidx * 4 + 2], 1e-7f), 0.1f));
        q3 = fmaxf(q3, fminf(fmaxf(epsf[hidx * 4 + 3], 1e-7f), 0.1f));
        inv = 1.f / (q0 + q1 + q2 + q3);
        float4 res = make_float4(q0 * inv, q1 * inv, q2 * inv, q3 * inv);
        int token2 = tok0 + tl2;
        *(float4*)&out[((size_t)token2 * 16 + hidx) * 4] = res;
    }
}

extern "C" void kernel_launch(void* const* d_in, const int* in_sizes, int n_in,
                              void* d_out, int out_size) {
    const float* hidden = (const float*)d_in[0];
    const float* br0    = (const float*)d_in[1];
    const float* br1    = (const float*)d_in[2];
    const float* br2    = (const float*)d_in[3];
    const float* br3    = (const float*)d_in[4];
    const float* W1     = (const float*)d_in[5];
    const float* b1     = (const float*)d_in[6];
    const float* W2     = (const float*)d_in[7];
    const float* b2     = (const float*)d_in[8];
    const float* epsf   = (const float*)d_in[9];
    const float* temp   = (const float*)d_in[10];
    float* out = (float*)d_out;

    const int smem_hid  = (2 * 32 * 64 + 2 * 64 * 128) * (int)sizeof(float);                 // 81920
    const int smem_tail = (64 * XSTRIDE + 64 * 12 + 8 * 16 * 4 + 2 * 64 * 128) * (int)sizeof(float); // 137216
    cudaFuncSetAttribute(k_hid,  cudaFuncAttributeMaxDynamicSharedMemorySize, smem_hid);
    cudaFuncSetAttribute(k_tail, cudaFuncAttributeMaxDynamicSharedMemorySize, smem_tail);

    k_hid<<<140, 128, smem_hid>>>(hidden, W1, b1);
    k_tail<<<1024, 256, smem_tail>>>(br0, br1, br2, br3, W1, W2, b2, epsf, temp, out);
}

// round 4
// speedup vs baseline: 1.2680x; 1.0448x over previous
#include <cuda_runtime.h>
#include <cuda_bf16.h>
#include <math.h>

typedef unsigned int uint32;

// ============================================================================
// HeadGroupedFusionGate via mma.sync bf16 3-term split (no tcgen05 on this
// toolchain: ptxas target is plain sm_103).
//   k_prep : W1 -> padded bf16 hi/lo B chunks [21][64][136] + statw colsums
//   k_hid  : hidden GEMM (M=4096,K=1024,N=128), K-split, partials to g_hidc*
//   k_tail : per-(token,head) GEMM (M=65536,K=4*64+stats,N=128) + epilogue
// ============================================================================

__device__ __nv_bfloat16 g_Wh[21 * 64 * 136];
__device__ __nv_bfloat16 g_Wl[21 * 64 * 136];
__device__ float g_hidcA[4096 * 128];
__device__ float g_hidcB[4096 * 128];

// ---- PTX helpers ----
__device__ __forceinline__ uint32 smem_u32(const void* p) {
    uint32 a;
    asm("{ .reg .u64 t; cvta.to.shared.u64 t, %1; cvt.u32.u64 %0, t; }" : "=r"(a) : "l"(p));
    return a;
}
__device__ __forceinline__ void cpa16(uint32 s, const void* g) {
    asm volatile("cp.async.cg.shared.global [%0], [%1], 16;" :: "r"(s), "l"(g));
}
#define CPA_COMMIT() asm volatile("cp.async.commit_group;")
#define CPA_WAIT0()  asm volatile("cp.async.wait_group 0;")
#define CPA_WAIT1()  asm volatile("cp.async.wait_group 1;")

__device__ __forceinline__ void ldsm4(uint32* r, uint32 a) {
    asm volatile("ldmatrix.sync.aligned.m8n8.x4.shared.b16 {%0,%1,%2,%3}, [%4];"
        : "=r"(r[0]), "=r"(r[1]), "=r"(r[2]), "=r"(r[3]) : "r"(a));
}
__device__ __forceinline__ void ldsm4t(uint32* r, uint32 a) {
    asm volatile("ldmatrix.sync.aligned.m8n8.x4.trans.shared.b16 {%0,%1,%2,%3}, [%4];"
        : "=r"(r[0]), "=r"(r[1]), "=r"(r[2]), "=r"(r[3]) : "r"(a));
}
__device__ __forceinline__ void mma16816(float* d, const uint32* a, uint32 b0, uint32 b1) {
    asm volatile("mma.sync.aligned.m16n8k16.row.col.f32.bf16.bf16.f32 "
        "{%0,%1,%2,%3}, {%4,%5,%6,%7}, {%8,%9}, {%0,%1,%2,%3};"
        : "+f"(d[0]), "+f"(d[1]), "+f"(d[2]), "+f"(d[3])
        : "r"(a[0]), "r"(a[1]), "r"(a[2]), "r"(a[3]), "r"(b0), "r"(b1));
}

// split pair (v0,v1) -> hi bf16x2 (rounded) + lo bf16x2 (rounded residual)
__device__ __forceinline__ void cvtpair(float v0, float v1, uint32& h, uint32& l) {
    __nv_bfloat162 hp = __floats2bfloat162_rn(v0, v1);
    h = *(uint32*)&hp;
    float r0 = v0 - __bfloat162float(hp.x);
    float r1 = v1 - __bfloat162float(hp.y);
    __nv_bfloat162 lp = __floats2bfloat162_rn(r0, r1);
    l = *(uint32*)&lp;
}

// ---- GEMM chunk: warp computes 16 rows x 128 cols over NK k16 steps, 3 terms
// A tiles row stride SA bytes; B tiles [64][136] bf16 (272 B rows).
template <int NK, int SA>
__device__ __forceinline__ void gemm_chunk(float (&acc)[16][4],
                                           uint32 Ah, uint32 Al,
                                           uint32 Bh, uint32 Bl, int lane) {
    uint32 aoff = (uint32)((lane & 15) * SA + (lane >> 4) * 16);
    uint32 boff = (uint32)(((lane & 7) + ((lane >> 3) & 1) * 8) * 272 + ((lane >> 4) & 1) * 16);
#pragma unroll
    for (int k = 0; k < NK; ++k) {
        uint32 ah[4], al[4];
        ldsm4(ah, Ah + aoff + k * 32);
        ldsm4(al, Al + aoff + k * 32);
#pragma unroll
        for (int g = 0; g < 4; ++g) {
            uint32 bh0[4], bh1[4], bl0[4], bl1[4];
            uint32 bb = boff + k * (16 * 272) + g * 64;
            ldsm4t(bh0, Bh + bb);
            ldsm4t(bh1, Bh + bb + 32);
            ldsm4t(bl0, Bl + bb);
            ldsm4t(bl1, Bl + bb + 32);
            mma16816(acc[4 * g + 0], ah, bh0[0], bh0[1]);
            mma16816(acc[4 * g + 1], ah, bh0[2], bh0[3]);
            mma16816(acc[4 * g + 2], ah, bh1[0], bh1[1]);
            mma16816(acc[4 * g + 3], ah, bh1[2], bh1[3]);
            mma16816(acc[4 * g + 0], al, bh0[0], bh0[1]);
            mma16816(acc[4 * g + 1], al, bh0[2], bh0[3]);
            mma16816(acc[4 * g + 2], al, bh1[0], bh1[1]);
            mma16816(acc[4 * g + 3], al, bh1[2], bh1[3]);
            mma16816(acc[4 * g + 0], ah, bl0[0], bl0[1]);
            mma16816(acc[4 * g + 1], ah, bl0[2], bl0[3]);
            mma16816(acc[4 * g + 2], ah, bl1[0], bl1[1]);
            mma16816(acc[4 * g + 3], ah, bl1[2], bl1[3]);
        }
    }
}

// ============================================================================
// k_prep: 21 chunks. c<16: hidden rows c*64; 16..19: tail rows 1792+(c-16)*64;
//         c==20: statw column sums (rows 0..11, 12..15 zero).
// ============================================================================
__global__ void __launch_bounds__(128) k_prep(const float* __restrict__ W1) {
    int c = blockIdx.x, o = threadIdx.x;
    if (c < 20) {
        int row0 = (c < 16) ? c * 64 : 1792 + (c - 16) * 64;
#pragma unroll 4
        for (int k = 0; k < 64; ++k) {
            float v = W1[(size_t)(row0 + k) * 128 + o];
            __nv_bfloat16 h = __float2bfloat16_rn(v);
            float r = v - __bfloat162float(h);
            g_Wh[(c * 64 + k) * 136 + o] = h;
            g_Wl[(c * 64 + k) * 136 + o] = __float2bfloat16_rn(r);
        }
    } else {
        for (int k = 0; k < 12; ++k) {
            int row0 = 1024 + (k / 3) * 192 + (k % 3) * 64;
            float s = 0.f;
#pragma unroll 8
            for (int d = 0; d < 64; ++d) s += W1[(size_t)(row0 + d) * 128 + o];
            __nv_bfloat16 h = __float2bfloat16_rn(s);
            float r = s - __bfloat162float(h);
            g_Wh[(20 * 64 + k) * 136 + o] = h;
            g_Wl[(20 * 64 + k) * 136 + o] = __float2bfloat16_rn(r);
        }
        __nv_bfloat16 z = __float2bfloat16_rn(0.f);
        for (int k = 12; k < 16; ++k) {
            g_Wh[(20 * 64 + k) * 136 + o] = z;
            g_Wl[(20 * 64 + k) * 136 + o] = z;
        }
    }
}

// ============================================================================
// k_hid: grid 128. bid>>1 = 64-token group, bid&1 = K half (8 chunks of 64).
//        128 thr = 4 warps x 16 token-rows. Writes partials to g_hidcA/B.
// smem: stage[2][16384] @0, Ahi @32768 (64x144), Alo @41984, B[2][2][17408] @51200
// ============================================================================
#define H_AHI 32768
#define H_ALO 41984
#define H_BB  51200
#define H_SMEM 120832

__global__ void __launch_bounds__(128) k_hid(const float* __restrict__ hidden) {
    extern __shared__ char sm[];
    uint32 sb = smem_u32(sm);
    int tid = threadIdx.x, lane = tid & 31, w = tid >> 5;
    int tg = blockIdx.x >> 1, khalf = blockIdx.x & 1;
    int tok0 = tg * 64;

    float acc[16][4];
#pragma unroll
    for (int j = 0; j < 16; ++j)
#pragma unroll
        for (int i = 0; i < 4; ++i) acc[j][i] = 0.f;

    // chunk loader: stage 1024 units, Bh/Bl 1088 units each
#define H_LOAD(cc, buf) do { \
        int c_ = khalf * 8 + (cc); \
        uint32 stg_ = sb + (buf) * 16384; \
        uint32 bh_ = sb + H_BB + (buf) * 34816, bl_ = bh_ + 17408; \
        const char* wh_ = (const char*)g_Wh + (size_t)c_ * 17408; \
        const char* wl_ = (const char*)g_Wl + (size_t)c_ * 17408; \
        for (int u = tid; u < 3200; u += 128) { \
            if (u < 1024) { \
                int row = u >> 4, seg = u & 15; \
                cpa16(stg_ + u * 16, (const char*)hidden + ((size_t)(tok0 + row) * 1024 + c_ * 64 + seg * 4) * 4); \
            } else if (u < 2112) cpa16(bh_ + (u - 1024) * 16, wh_ + (size_t)(u - 1024) * 16); \
            else cpa16(bl_ + (u - 2112) * 16, wl_ + (size_t)(u - 2112) * 16); \
        } \
        CPA_COMMIT(); \
    } while (0)

    H_LOAD(0, 0);
    for (int p = 0; p < 8; ++p) {
        __syncthreads();
        if (p < 7) { H_LOAD(p + 1, (p + 1) & 1); CPA_WAIT1(); }
        else CPA_WAIT0();
        __syncthreads();
        // convert stage -> Ahi/Alo (64x144 layout)
        {
            const float* stg = (const float*)(sm + (p & 1) * 16384);
#pragma unroll
            for (int i = 0; i < 8; ++i) {
                int u = tid + 128 * i;                 // 1024 float4 units
                float4 v = ((const float4*)stg)[u];
                uint32 h0, l0, h1, l1;
                cvtpair(v.x, v.y, h0, l0);
                cvtpair(v.z, v.w, h1, l1);
                int row = u >> 4, seg = u & 15;
                *(uint2*)(sm + H_AHI + row * 144 + seg * 8) = make_uint2(h0, h1);
                *(uint2*)(sm + H_ALO + row * 144 + seg * 8) = make_uint2(l0, l1);
            }
        }
        __syncthreads();
        gemm_chunk<4, 144>(acc, sb + H_AHI + w * 16 * 144, sb + H_ALO + w * 16 * 144,
                           sb + H_BB + (p & 1) * 34816, sb + H_BB + (p & 1) * 34816 + 17408, lane);
    }

    // write partials
    float* dst = khalf ? g_hidcB : g_hidcA;
    int q = lane >> 2, c2 = (lane & 3) * 2;
    int rowg = tok0 + w * 16;
#pragma unroll
    for (int j = 0; j < 16; ++j) {
        int col = j * 8 + c2;
        *(float2*)&dst[(size_t)(rowg + q) * 128 + col] = make_float2(acc[j][0], acc[j][1]);
        *(float2*)&dst[(size_t)(rowg + q + 8) * 128 + col] = make_float2(acc[j][2], acc[j][3]);
    }
#undef H_LOAD
}

// ============================================================================
// k_tail: grid 512, 256 thr = 8 warps. CTA = 8 tokens x 16 heads = 128 rows.
//   chunks p=0..3: branch p (K=64); p=4: stats (K=16).
// smem map:
//   0       stage[2][32768]
//   65536   Ahi (128x144)      83968  Alo
//   102400  B[2][2][17408]
//   172032  AstatHi (128x48)   178176 AstatLo
//   184320  hids (8x128 f32)   188416 W2s (128x4)   190464 misc
// ============================================================================
#define T_AHI 65536
#define T_ALO 83968
#define T_BB  102400
#define T_ASH 172032
#define T_ASL 178176
#define T_HID 184320
#define T_W2S 188416
#define T_MSC 190464
#define T_SMEM 190976

__global__ void __launch_bounds__(256) k_tail(
    const float* __restrict__ br0, const float* __restrict__ br1,
    const float* __restrict__ br2, const float* __restrict__ br3,
    const float* __restrict__ b1, const float* __restrict__ W2,
    const float* __restrict__ b2, const float* __restrict__ epsf,
    const float* __restrict__ temp, float* __restrict__ out) {
    extern __shared__ char sm[];
    uint32 sb = smem_u32(sm);
    int tid = threadIdx.x, lane = tid & 31, w = tid >> 5;
    int tok0 = blockIdx.x * 8;
    const float* brs[4] = {br0, br1, br2, br3};

    // epilogue staging (visible after first __syncthreads in loop)
    {
        int row = tid >> 5, c4 = tid & 31;           // hids = hidA+hidB+b1
        float4 a = *(const float4*)&g_hidcA[(size_t)(tok0 + row) * 128 + c4 * 4];
        float4 b = *(const float4*)&g_hidcB[(size_t)(tok0 + row) * 128 + c4 * 4];
        float4 c = ((const float4*)b1)[c4];
        *(float4*)(sm + T_HID + tid * 16) =
            make_float4(a.x + b.x + c.x, a.y + b.y + c.y, a.z + b.z + c.z, a.w + b.w + c.w);
        if (tid < 128) *(float4*)(sm + T_W2S + tid * 16) = ((const float4*)W2)[tid];
        float* msc = (float*)(sm + T_MSC);
        if (tid < 4)  msc[tid] = b2[tid];
        if (tid < 16) msc[4 + tid] = temp[tid];
        if (tid < 64) msc[20 + tid] = epsf[tid];
    }

    float acc[16][4];
#pragma unroll
    for (int j = 0; j < 16; ++j)
#pragma unroll
        for (int i = 0; i < 4; ++i) acc[j][i] = 0.f;
    float sv[12];

#define T_LOAD(p_, buf) do { \
        uint32 bh_ = sb + T_BB + (buf) * 34816, bl_ = bh_ + 17408; \
        if ((p_) < 4) { \
            const char* src_ = (const char*)brs[p_] + (size_t)tok0 * 16 * 256; \
            const char* wh_ = (const char*)g_Wh + (size_t)(16 + (p_)) * 17408; \
            const char* wl_ = (const char*)g_Wl + (size_t)(16 + (p_)) * 17408; \
            uint32 stg_ = sb + (buf) * 32768; \
            for (int u = tid; u < 4224; u += 256) { \
                if (u < 2048) cpa16(stg_ + u * 16, src_ + (size_t)u * 16); \
                else if (u < 3136) cpa16(bh_ + (u - 2048) * 16, wh_ + (size_t)(u - 2048) * 16); \
                else cpa16(bl_ + (u - 3136) * 16, wl_ + (size_t)(u - 3136) * 16); \
            } \
        } else { \
            const char* wh_ = (const char*)g_Wh + (size_t)20 * 17408; \
            const char* wl_ = (const char*)g_Wl + (size_t)20 * 17408; \
            for (int u = tid; u < 544; u += 256) { \
                if (u < 272) cpa16(bh_ + u * 16, wh_ + (size_t)u * 16); \
                else cpa16(bl_ + (u - 272) * 16, wl_ + (size_t)(u - 272) * 16); \
            } \
        } \
        CPA_COMMIT(); \
    } while (0)

    T_LOAD(0, 0);
    for (int p = 0; p <= 4; ++p) {
        __syncthreads();
        if (p < 4) { T_LOAD(p + 1, (p + 1) & 1); CPA_WAIT1(); }
        else CPA_WAIT0();
        __syncthreads();
        if (p < 4) {
            const float* stg = (const float*)(sm + (p & 1) * 32768);
            if (tid < 128) {                       // stats for row tid
                const float4* xr = (const float4*)stg + tid * 16;
                float s = 0.f, s2 = 0.f, mx = -INFINITY;
#pragma unroll
                for (int j = 0; j < 16; ++j) {
                    float4 v = xr[j];
                    s += v.x + v.y + v.z + v.w;
                    s2 = fmaf(v.x, v.x, fmaf(v.y, v.y, fmaf(v.z, v.z, fmaf(v.w, v.w, s2))));
                    mx = fmaxf(mx, fmaxf(fmaxf(v.x, v.y), fmaxf(v.z, v.w)));
                }
                sv[p * 3 + 0] = s * 0.015625f;
                sv[p * 3 + 1] = sqrtf(fmaxf(s2 * 0.015625f, 1e-8f));
                sv[p * 3 + 2] = mx;
            }
#pragma unroll
            for (int i = 0; i < 8; ++i) {          // convert 2048 units
                int u = tid + 256 * i;
                float4 v = ((const float4*)stg)[u];
                uint32 h0, l0, h1, l1;
                cvtpair(v.x, v.y, h0, l0);
                cvtpair(v.z, v.w, h1, l1);
                int row = u >> 4, seg = u & 15;
                *(uint2*)(sm + T_AHI + row * 144 + seg * 8) = make_uint2(h0, h1);
                *(uint2*)(sm + T_ALO + row * 144 + seg * 8) = make_uint2(l0, l1);
            }
            if (p == 3 && tid < 128) {             // emit stats rows (cols 0..15)
                uint32 hh[8], ll[8];
#pragma unroll
                for (int j = 0; j < 6; ++j) cvtpair(sv[2 * j], sv[2 * j + 1], hh[j], ll[j]);
                hh[6] = hh[7] = ll[6] = ll[7] = 0u;
                *(uint4*)(sm + T_ASH + tid * 48)      = make_uint4(hh[0], hh[1], hh[2], hh[3]);
                *(uint4*)(sm + T_ASH + tid * 48 + 16) = make_uint4(hh[4], hh[5], hh[6], hh[7]);
                *(uint4*)(sm + T_ASL + tid * 48)      = make_uint4(ll[0], ll[1], ll[2], ll[3]);
                *(uint4*)(sm + T_ASL + tid * 48 + 16) = make_uint4(ll[4], ll[5], ll[6], ll[7]);
            }
        }
        __syncthreads();
        if (p < 4)
            gemm_chunk<4, 144>(acc, sb + T_AHI + w * 16 * 144, sb + T_ALO + w * 16 * 144,
                               sb + T_BB + (p & 1) * 34816, sb + T_BB + (p & 1) * 34816 + 17408, lane);
        else
            gemm_chunk<1, 48>(acc, sb + T_ASH + w * 16 * 48, sb + T_ASL + w * 16 * 48,
                              sb + T_BB, sb + T_BB + 17408, lane);
    }
#undef T_LOAD

    // ---- epilogue: gelu + W2 + softmax/floor ----
    int q = lane >> 2, c2 = (lane & 3) * 2;
    float lgA[4] = {0.f, 0.f, 0.f, 0.f};
    float lgB[4] = {0.f, 0.f, 0.f, 0.f};
#pragma unroll
    for (int j = 0; j < 16; ++j) {
        int col = j * 8 + c2;
        float2 hv = *(const float2*)(sm + T_HID + (w * 128 + col) * 4);
        float v00 = acc[j][0] + hv.x, v01 = acc[j][1] + hv.y;
        float v10 = acc[j][2] + hv.x, v11 = acc[j][3] + hv.y;
        float g00 = v00 * normcdff(v00), g01 = v01 * normcdff(v01);
        float g10 = v10 * normcdff(v10), g11 = v11 * normcdff(v11);
        float4 wa = *(const float4*)(sm + T_W2S + col * 16);
        float4 wb = *(const float4*)(sm + T_W2S + (col + 1) * 16);
        lgA[0] = fmaf(g00, wa.x, fmaf(g01, wb.x, lgA[0]));
        lgA[1] = fmaf(g00, wa.y, fmaf(g01, wb.y, lgA[1]));
        lgA[2] = fmaf(g00, wa.z, fmaf(g01, wb.z, lgA[2]));
        lgA[3] = fmaf(g00, wa.w, fmaf(g01, wb.w, lgA[3]));
        lgB[0] = fmaf(g10, wa.x, fmaf(g11, wb.x, lgB[0]));
        lgB[1] = fmaf(g10, wa.y, fmaf(g11, wb.y, lgB[1]));
        lgB[2] = fmaf(g10, wa.z, fmaf(g11, wb.z, lgB[2]));
        lgB[3] = fmaf(g10, wa.w, fmaf(g11, wb.w, lgB[3]));
    }
#pragma unroll
    for (int d = 1; d <= 2; d <<= 1) {
#pragma unroll
        for (int i = 0; i < 4; ++i) {
            lgA[i] += __shfl_xor_sync(0xffffffffu, lgA[i], d);
            lgB[i] += __shfl_xor_sync(0xffffffffu, lgB[i], d);
        }
    }
    if ((lane & 3) == 0) {
        const float* msc = (const float*)(sm + T_MSC);
#pragma unroll
        for (int half = 0; half < 2; ++half) {
            int h = q + half * 8;
            float* lg = half ? lgB : lgA;
            float l0 = lg[0] + msc[0], l1 = lg[1] + msc[1];
            float l2 = lg[2] + msc[2], l3 = lg[3] + msc[3];
            float tt = fminf(fmaxf(msc[4 + h], 0.2f), 10.f);
            float it = 1.f / tt;
            float m = fmaxf(fmaxf(l0, l1), fmaxf(l2, l3));
            float e0 = expf((l0 - m) * it), e1 = expf((l1 - m) * it);
            float e2 = expf((l2 - m) * it), e3 = expf((l3 - m) * it);
            float inv = 1.f / (e0 + e1 + e2 + e3);
            float q0 = e0 * inv, q1 = e1 * inv, q2 = e2 * inv, q3 = e3 * inv;
            q0 = fmaxf(q0, fminf(fmaxf(msc[20 + h * 4 + 0], 1e-7f), 0.1f));
            q1 = fmaxf(q1, fminf(fmaxf(msc[20 + h * 4 + 1], 1e-7f), 0.1f));
            q2 = fmaxf(q2, fminf(fmaxf(msc[20 + h * 4 + 2], 1e-7f), 0.1f));
            q3 = fmaxf(q3, fminf(fmaxf(msc[20 + h * 4 + 3], 1e-7f), 0.1f));
            inv = 1.f / (q0 + q1 + q2 + q3);
            *(float4*)&out[((size_t)(tok0 + w) * 16 + h) * 4] =
                make_float4(q0 * inv, q1 * inv, q2 * inv, q3 * inv);
        }
    }
}

extern "C" void kernel_launch(void* const* d_in, const int* in_sizes, int n_in,
                              void* d_out, int out_size) {
    const float* hidden = (const float*)d_in[0];
    const float* br0    = (const float*)d_in[1];
    const float* br1    = (const float*)d_in[2];
    const float* br2    = (const float*)d_in[3];
    const float* br3    = (const float*)d_in[4];
    const float* W1     = (const float*)d_in[5];
    const float* b1     = (const float*)d_in[6];
    const float* W2     = (const float*)d_in[7];
    const float* b2     = (const float*)d_in[8];
    const float* epsf   = (const float*)d_in[9];
    const float* temp   = (const float*)d_in[10];
    float* out = (float*)d_out;

    cudaFuncSetAttribute(k_hid,  cudaFuncAttributeMaxDynamicSharedMemorySize, H_SMEM);
    cudaFuncSetAttribute(k_tail, cudaFuncAttributeMaxDynamicSharedMemorySize, T_SMEM);

    k_prep<<<21, 128>>>(W1);
    k_hid<<<128, 128, H_SMEM>>>(hidden);
    k_tail<<<512, 256, T_SMEM>>>(br0, br1, br2, br3, b1, W2, b2, epsf, temp, out);
}

// round 5
// speedup vs baseline: 2.7466x; 2.1661x over previous
#include <cuda_runtime.h>
#include <cuda_bf16.h>
#include <math.h>

typedef unsigned int uint32;

// ============================================================================
// HeadGroupedFusionGate via mma.sync bf16 3-term split (x*w ~ xh*wh+xl*wh+xh*wl).
//   k_prep : W1 -> padded bf16 hi/lo B chunks [21][64][136] + statw colsums
//   k_hid  : hidden GEMM (M=4096,K=1024,N=128), K-split, partials to g_hidc*
//   k_tail : per-(token,head) GEMM (M=65536,K=4*64+stats,N=128) + epilogue
// R5: parallel k_prep; register-direct convert (no fp32 stage smem);
//     k_tail 90.6KB smem -> 2 CTA/SM, k_hid 53KB -> 4 CTA/SM.
// ============================================================================

__device__ __nv_bfloat16 g_Wh[21 * 64 * 136];
__device__ __nv_bfloat16 g_Wl[21 * 64 * 136];
__device__ float g_hidcA[4096 * 128];
__device__ float g_hidcB[4096 * 128];

// ---- PTX helpers ----
__device__ __forceinline__ uint32 smem_u32(const void* p) {
    uint32 a;
    asm("{ .reg .u64 t; cvta.to.shared.u64 t, %1; cvt.u32.u64 %0, t; }" : "=r"(a) : "l"(p));
    return a;
}
__device__ __forceinline__ void cpa16(uint32 s, const void* g) {
    asm volatile("cp.async.cg.shared.global [%0], [%1], 16;" :: "r"(s), "l"(g));
}
#define CPA_COMMIT() asm volatile("cp.async.commit_group;")
#define CPA_WAIT0()  asm volatile("cp.async.wait_group 0;")

__device__ __forceinline__ void ldsm4(uint32* r, uint32 a) {
    asm volatile("ldmatrix.sync.aligned.m8n8.x4.shared.b16 {%0,%1,%2,%3}, [%4];"
        : "=r"(r[0]), "=r"(r[1]), "=r"(r[2]), "=r"(r[3]) : "r"(a));
}
__device__ __forceinline__ void ldsm4t(uint32* r, uint32 a) {
    asm volatile("ldmatrix.sync.aligned.m8n8.x4.trans.shared.b16 {%0,%1,%2,%3}, [%4];"
        : "=r"(r[0]), "=r"(r[1]), "=r"(r[2]), "=r"(r[3]) : "r"(a));
}
__device__ __forceinline__ void mma16816(float* d, const uint32* a, uint32 b0, uint32 b1) {
    asm volatile("mma.sync.aligned.m16n8k16.row.col.f32.bf16.bf16.f32 "
        "{%0,%1,%2,%3}, {%4,%5,%6,%7}, {%8,%9}, {%0,%1,%2,%3};"
        : "+f"(d[0]), "+f"(d[1]), "+f"(d[2]), "+f"(d[3])
        : "r"(a[0]), "r"(a[1]), "r"(a[2]), "r"(a[3]), "r"(b0), "r"(b1));
}
__device__ __forceinline__ void cvtpair(float v0, float v1, uint32& h, uint32& l) {
    __nv_bfloat162 hp = __floats2bfloat162_rn(v0, v1);
    h = *(uint32*)&hp;
    float r0 = v0 - __bfloat162float(hp.x);
    float r1 = v1 - __bfloat162float(hp.y);
    __nv_bfloat162 lp = __floats2bfloat162_rn(r0, r1);
    l = *(uint32*)&lp;
}

// ---- GEMM chunk: warp computes 16 rows x 128 cols over NK k16 steps, 3 terms
template <int NK, int SA>
__device__ __forceinline__ void gemm_chunk(float (&acc)[16][4],
                                           uint32 Ah, uint32 Al,
                                           uint32 Bh, uint32 Bl, int lane) {
    uint32 aoff = (uint32)((lane & 15) * SA + (lane >> 4) * 16);
    uint32 boff = (uint32)(((lane & 7) + ((lane >> 3) & 1) * 8) * 272 + ((lane >> 4) & 1) * 16);
#pragma unroll
    for (int k = 0; k < NK; ++k) {
        uint32 ah[4], al[4];
        ldsm4(ah, Ah + aoff + k * 32);
        ldsm4(al, Al + aoff + k * 32);
#pragma unroll
        for (int g = 0; g < 4; ++g) {
            uint32 bh0[4], bh1[4], bl0[4], bl1[4];
            uint32 bb = boff + k * (16 * 272) + g * 64;
            ldsm4t(bh0, Bh + bb);
            ldsm4t(bh1, Bh + bb + 32);
            ldsm4t(bl0, Bl + bb);
            ldsm4t(bl1, Bl + bb + 32);
            mma16816(acc[4 * g + 0], ah, bh0[0], bh0[1]);
            mma16816(acc[4 * g + 1], ah, bh0[2], bh0[3]);
            mma16816(acc[4 * g + 2], ah, bh1[0], bh1[1]);
            mma16816(acc[4 * g + 3], ah, bh1[2], bh1[3]);
            mma16816(acc[4 * g + 0], al, bh0[0], bh0[1]);
            mma16816(acc[4 * g + 1], al, bh0[2], bh0[3]);
            mma16816(acc[4 * g + 2], al, bh1[0], bh1[1]);
            mma16816(acc[4 * g + 3], al, bh1[2], bh1[3]);
            mma16816(acc[4 * g + 0], ah, bl0[0], bl0[1]);
            mma16816(acc[4 * g + 1], ah, bl0[2], bl0[3]);
            mma16816(acc[4 * g + 2], ah, bl1[0], bl1[1]);
            mma16816(acc[4 * g + 3], ah, bl1[2], bl1[3]);
        }
    }
}

// ============================================================================
// k_prep: grid 173. b<160: 8 W1 rows each (coalesced). 160..171: statw colsum k.
//         172: zero stats pad rows 12..15.
// ============================================================================
__global__ void __launch_bounds__(128) k_prep(const float* __restrict__ W1) {
    int b = blockIdx.x, tid = threadIdx.x;
    if (b < 160) {
        int rr0 = b * 8;
#pragma unroll
        for (int j = 0; j < 8; ++j) {
            int rr = rr0 + j;                 // chunk-row index 0..1279
            int c = rr >> 6, k = rr & 63;
            int row = (c < 16) ? c * 64 + k : 1792 + (c - 16) * 64 + k;
            float v = W1[(size_t)row * 128 + tid];
            __nv_bfloat16 h = __float2bfloat16_rn(v);
            g_Wh[rr * 136 + tid] = h;
            g_Wl[rr * 136 + tid] = __float2bfloat16_rn(v - __bfloat162float(h));
        }
    } else if (b < 172) {
        int k = b - 160;
        int row0 = 1024 + (k / 3) * 192 + (k % 3) * 64;
        float s = 0.f;
#pragma unroll 8
        for (int d = 0; d < 64; ++d) s += W1[(size_t)(row0 + d) * 128 + tid];
        __nv_bfloat16 h = __float2bfloat16_rn(s);
        g_Wh[(1280 + k) * 136 + tid] = h;
        g_Wl[(1280 + k) * 136 + tid] = __float2bfloat16_rn(s - __bfloat162float(h));
    } else {
        __nv_bfloat16 z = __float2bfloat16_rn(0.f);
#pragma unroll
        for (int k = 12; k < 16; ++k) {
            g_Wh[(1280 + k) * 136 + tid] = z;
            g_Wl[(1280 + k) * 136 + tid] = z;
        }
    }
}

// ============================================================================
// k_hid: grid 128 (bid>>1 = 64-token group, bid&1 = K half), 128 thr = 4 warps.
// smem: Ahi 0 (64x144=9216), Alo 9216, Bh 18432 (17408), Bl 35840. Total 53248.
// ============================================================================
#define H_ALO 9216
#define H_BH  18432
#define H_BL  35840
#define H_SMEM 53248

__global__ void __launch_bounds__(128, 4) k_hid(const float* __restrict__ hidden) {
    extern __shared__ char sm[];
    uint32 sb = smem_u32(sm);
    int tid = threadIdx.x, lane = tid & 31, w = tid >> 5;
    int tg = blockIdx.x >> 1, khalf = blockIdx.x & 1;
    int tok0 = tg * 64;

    float acc[16][4];
#pragma unroll
    for (int j = 0; j < 16; ++j)
#pragma unroll
        for (int i = 0; i < 4; ++i) acc[j][i] = 0.f;

    for (int p = 0; p < 8; ++p) {
        int c = khalf * 8 + p;
        __syncthreads();                          // A/B free (prev mma done)
        // B chunk cp.async (single buffer)
        {
            const char* wh = (const char*)g_Wh + (size_t)c * 17408;
            const char* wl = (const char*)g_Wl + (size_t)c * 17408;
            for (int u = tid; u < 1088; u += 128) cpa16(sb + H_BH + u * 16, wh + (size_t)u * 16);
            for (int u = tid; u < 1088; u += 128) cpa16(sb + H_BL + u * 16, wl + (size_t)u * 16);
            CPA_COMMIT();
        }
        // hidden tile -> regs -> convert -> A tiles
        {
            float4 f[8];
            const float4* src = (const float4*)hidden + (size_t)tok0 * 256 + c * 16;
#pragma unroll
            for (int i = 0; i < 8; ++i) {
                int u = tid + 128 * i;
                int row = u >> 4, seg = u & 15;
                f[i] = src[(size_t)row * 256 + seg];
            }
#pragma unroll
            for (int i = 0; i < 8; ++i) {
                int u = tid + 128 * i;
                int row = u >> 4, seg = u & 15;
                uint32 h0, l0, h1, l1;
                cvtpair(f[i].x, f[i].y, h0, l0);
                cvtpair(f[i].z, f[i].w, h1, l1);
                *(uint2*)(sm + row * 144 + seg * 8) = make_uint2(h0, h1);
                *(uint2*)(sm + H_ALO + row * 144 + seg * 8) = make_uint2(l0, l1);
            }
        }
        CPA_WAIT0();
        __syncthreads();
        gemm_chunk<4, 144>(acc, sb + w * 16 * 144, sb + H_ALO + w * 16 * 144,
                           sb + H_BH, sb + H_BL, lane);
    }

    float* dst = khalf ? g_hidcB : g_hidcA;
    int q = lane >> 2, c2 = (lane & 3) * 2;
    int rowg = tok0 + w * 16;
#pragma unroll
    for (int j = 0; j < 16; ++j) {
        int col = j * 8 + c2;
        *(float2*)&dst[(size_t)(rowg + q) * 128 + col] = make_float2(acc[j][0], acc[j][1]);
        *(float2*)&dst[(size_t)(rowg + q + 8) * 128 + col] = make_float2(acc[j][2], acc[j][3]);
    }
}

// ============================================================================
// k_tail: grid 512, 256 thr = 8 warps. CTA = 8 tokens x 16 heads = 128 rows.
// smem map (bytes):
//   Ahi 0 (128x144=18432)  Alo 18432  Bh 36864 (17408)  Bl 54272
//   ASH 71680 (128x48)     ASL 77824  HID 83968 (4KB)   W2S 88064  MSC 90112
// ============================================================================
#define T_ALO 18432
#define T_BH  36864
#define T_BL  54272
#define T_ASH 71680
#define T_ASL 77824
#define T_HID 83968
#define T_W2S 88064
#define T_MSC 90112
#define T_SMEM 90624

__global__ void __launch_bounds__(256, 2) k_tail(
    const float* __restrict__ br0, const float* __restrict__ br1,
    const float* __restrict__ br2, const float* __restrict__ br3,
    const float* __restrict__ b1, const float* __restrict__ W2,
    const float* __restrict__ b2, const float* __restrict__ epsf,
    const float* __restrict__ temp, float* __restrict__ out) {
    extern __shared__ char sm[];
    uint32 sb = smem_u32(sm);
    int tid = threadIdx.x, lane = tid & 31, w = tid >> 5;
    int tok0 = blockIdx.x * 8;
    const float* brs[4] = {br0, br1, br2, br3};

    // prologue: epilogue data + stat-tile zero pad (cols 12..15)
    {
        int row = tid >> 5, c4 = tid & 31;
        float4 a = *(const float4*)&g_hidcA[(size_t)(tok0 + row) * 128 + c4 * 4];
        float4 b = *(const float4*)&g_hidcB[(size_t)(tok0 + row) * 128 + c4 * 4];
        float4 c = ((const float4*)b1)[c4];
        *(float4*)(sm + T_HID + tid * 16) =
            make_float4(a.x + b.x + c.x, a.y + b.y + c.y, a.z + b.z + c.z, a.w + b.w + c.w);
        if (tid < 128) {
            *(float4*)(sm + T_W2S + tid * 16) = ((const float4*)W2)[tid];
            *(uint2*)(sm + T_ASH + tid * 48 + 24) = make_uint2(0u, 0u);
            *(uint2*)(sm + T_ASL + tid * 48 + 24) = make_uint2(0u, 0u);
        }
        float* msc = (float*)(sm + T_MSC);
        if (tid < 4)  msc[tid] = b2[tid];
        if (tid < 16) msc[4 + tid] = temp[tid];
        if (tid < 64) msc[20 + tid] = epsf[tid];
    }

    float acc[16][4];
#pragma unroll
    for (int j = 0; j < 16; ++j)
#pragma unroll
        for (int i = 0; i < 4; ++i) acc[j][i] = 0.f;

    for (int p = 0; p < 5; ++p) {
        __syncthreads();                          // prev mma done: A/B/stat free
        if (p < 4) {
            // B chunk cp.async
            {
                const char* wh = (const char*)g_Wh + (size_t)(16 + p) * 17408;
                const char* wl = (const char*)g_Wl + (size_t)(16 + p) * 17408;
                for (int u = tid; u < 1088; u += 256) cpa16(sb + T_BH + u * 16, wh + (size_t)u * 16);
                for (int u = tid; u < 1088; u += 256) cpa16(sb + T_BL + u * 16, wl + (size_t)u * 16);
                CPA_COMMIT();
            }
            // branch tile -> regs
            float4 f[8];
            const float4* src = (const float4*)brs[p] + (size_t)tok0 * 256;
#pragma unroll
            for (int i = 0; i < 8; ++i) f[i] = src[tid + 256 * i];
            // stats (half-warp reduce) + convert -> A tiles
#pragma unroll
            for (int i = 0; i < 8; ++i) {
                float4 v = f[i];
                int row = (tid >> 4) + 16 * i, seg = tid & 15;
                float s = v.x + v.y + v.z + v.w;
                float s2 = fmaf(v.x, v.x, fmaf(v.y, v.y, fmaf(v.z, v.z, v.w * v.w)));
                float mx = fmaxf(fmaxf(v.x, v.y), fmaxf(v.z, v.w));
#pragma unroll
                for (int d = 1; d <= 8; d <<= 1) {
                    s += __shfl_xor_sync(0xffffffffu, s, d);
                    s2 += __shfl_xor_sync(0xffffffffu, s2, d);
                    mx = fmaxf(mx, __shfl_xor_sync(0xffffffffu, mx, d));
                }
                if (seg < 3) {
                    float sval = (seg == 0) ? s * 0.015625f
                               : (seg == 1) ? sqrtf(fmaxf(s2 * 0.015625f, 1e-8f)) : mx;
                    __nv_bfloat16 h = __float2bfloat16_rn(sval);
                    float r = sval - __bfloat162float(h);
                    *(__nv_bfloat16*)(sm + T_ASH + row * 48 + (p * 3 + seg) * 2) = h;
                    *(__nv_bfloat16*)(sm + T_ASL + row * 48 + (p * 3 + seg) * 2) = __float2bfloat16_rn(r);
                }
                uint32 h0, l0, h1, l1;
                cvtpair(v.x, v.y, h0, l0);
                cvtpair(v.z, v.w, h1, l1);
                *(uint2*)(sm + row * 144 + seg * 8) = make_uint2(h0, h1);
                *(uint2*)(sm + T_ALO + row * 144 + seg * 8) = make_uint2(l0, l1);
            }
            CPA_WAIT0();
            __syncthreads();
            gemm_chunk<4, 144>(acc, sb + w * 16 * 144, sb + T_ALO + w * 16 * 144,
                               sb + T_BH, sb + T_BL, lane);
        } else {
            // stats chunk: B = statw (16 K-rows)
            const char* wh = (const char*)g_Wh + (size_t)20 * 17408;
            const char* wl = (const char*)g_Wl + (size_t)20 * 17408;
            for (int u = tid; u < 272; u += 256) cpa16(sb + T_BH + u * 16, wh + (size_t)u * 16);
            for (int u = tid; u < 272; u += 256) cpa16(sb + T_BL + u * 16, wl + (size_t)u * 16);
            CPA_COMMIT(); CPA_WAIT0();
            __syncthreads();
            gemm_chunk<1, 48>(acc, sb + T_ASH + w * 16 * 48, sb + T_ASL + w * 16 * 48,
                              sb + T_BH, sb + T_BL, lane);
        }
    }

    // ---- epilogue: gelu + W2 + softmax/floor ----
    int q = lane >> 2, c2 = (lane & 3) * 2;
    float lgA[4] = {0.f, 0.f, 0.f, 0.f};
    float lgB[4] = {0.f, 0.f, 0.f, 0.f};
#pragma unroll
    for (int j = 0; j < 16; ++j) {
        int col = j * 8 + c2;
        float2 hv = *(const float2*)(sm + T_HID + (w * 128 + col) * 4);
        float v00 = acc[j][0] + hv.x, v01 = acc[j][1] + hv.y;
        float v10 = acc[j][2] + hv.x, v11 = acc[j][3] + hv.y;
        float g00 = v00 * normcdff(v00), g01 = v01 * normcdff(v01);
        float g10 = v10 * normcdff(v10), g11 = v11 * normcdff(v11);
        float4 wa = *(const float4*)(sm + T_W2S + col * 16);
        float4 wb = *(const float4*)(sm + T_W2S + (col + 1) * 16);
        lgA[0] = fmaf(g00, wa.x, fmaf(g01, wb.x, lgA[0]));
        lgA[1] = fmaf(g00, wa.y, fmaf(g01, wb.y, lgA[1]));
        lgA[2] = fmaf(g00, wa.z, fmaf(g01, wb.z, lgA[2]));
        lgA[3] = fmaf(g00, wa.w, fmaf(g01, wb.w, lgA[3]));
        lgB[0] = fmaf(g10, wa.x, fmaf(g11, wb.x, lgB[0]));
        lgB[1] = fmaf(g10, wa.y, fmaf(g11, wb.y, lgB[1]));
        lgB[2] = fmaf(g10, wa.z, fmaf(g11, wb.z, lgB[2]));
        lgB[3] = fmaf(g10, wa.w, fmaf(g11, wb.w, lgB[3]));
    }
#pragma unroll
    for (int d = 1; d <= 2; d <<= 1) {
#pragma unroll
        for (int i = 0; i < 4; ++i) {
            lgA[i] += __shfl_xor_sync(0xffffffffu, lgA[i], d);
            lgB[i] += __shfl_xor_sync(0xffffffffu, lgB[i], d);
        }
    }
    if ((lane & 3) == 0) {
        const float* msc = (const float*)(sm + T_MSC);
#pragma unroll
        for (int half = 0; half < 2; ++half) {
            int h = q + half * 8;
            float* lg = half ? lgB : lgA;
            float l0 = lg[0] + msc[0], l1 = lg[1] + msc[1];
            float l2 = lg[2] + msc[2], l3 = lg[3] + msc[3];
            float tt = fminf(fmaxf(msc[4 + h], 0.2f), 10.f);
            float it = 1.f / tt;
            float m = fmaxf(fmaxf(l0, l1), fmaxf(l2, l3));
            float e0 = expf((l0 - m) * it), e1 = expf((l1 - m) * it);
            float e2 = expf((l2 - m) * it), e3 = expf((l3 - m) * it);
            float inv = 1.f / (e0 + e1 + e2 + e3);
            float q0 = e0 * inv, q1 = e1 * inv, q2 = e2 * inv, q3 = e3 * inv;
            q0 = fmaxf(q0, fminf(fmaxf(msc[20 + h * 4 + 0], 1e-7f), 0.1f));
            q1 = fmaxf(q1, fminf(fmaxf(msc[20 + h * 4 + 1], 1e-7f), 0.1f));
            q2 = fmaxf(q2, fminf(fmaxf(msc[20 + h * 4 + 2], 1e-7f), 0.1f));
            q3 = fmaxf(q3, fminf(fmaxf(msc[20 + h * 4 + 3], 1e-7f), 0.1f));
            inv = 1.f / (q0 + q1 + q2 + q3);
            *(float4*)&out[((size_t)(tok0 + w) * 16 + h) * 4] =
                make_float4(q0 * inv, q1 * inv, q2 * inv, q3 * inv);
        }
    }
}

extern "C" void kernel_launch(void* const* d_in, const int* in_sizes, int n_in,
                              void* d_out, int out_size) {
    const float* hidden = (const float*)d_in[0];
    const float* br0    = (const float*)d_in[1];
    const float* br1    = (const float*)d_in[2];
    const float* br2    = (const float*)d_in[3];
    const float* br3    = (const float*)d_in[4];
    const float* W1     = (const float*)d_in[5];
    const float* b1     = (const float*)d_in[6];
    const float* W2     = (const float*)d_in[7];
    const float* b2     = (const float*)d_in[8];
    const float* epsf   = (const float*)d_in[9];
    const float* temp   = (const float*)d_in[10];
    float* out = (float*)d_out;

    cudaFuncSetAttribute(k_hid,  cudaFuncAttributeMaxDynamicSharedMemorySize, H_SMEM);
    cudaFuncSetAttribute(k_tail, cudaFuncAttributeMaxDynamicSharedMemorySize, T_SMEM);

    k_prep<<<173, 128>>>(W1);
    k_hid<<<128, 128, H_SMEM>>>(hidden);
    k_tail<<<512, 256, T_SMEM>>>(br0, br1, br2, br3, b1, W2, b2, epsf, temp, out);
}